// round 3
// baseline (speedup 1.0000x reference)
#include <cuda_runtime.h>
#include <cstdint>
#include <cstddef>

// Problem constants (fixed by the dataset)
#define K_   512      // num_embeddings
#define D_   64       // embedding_dim
#define N_   262144   // H*W = 512*512
#define BM   128      // points per block
#define KC   128      // codes per chunk
#define NCH  (K_ / KC)
#define THREADS 256
#define ZS   66       // sz row stride in floats
#define CS   132      // sc row stride in floats (16B-aligned rows)

// ---- device scratch (no allocations allowed) ----
__device__ float g_bcs[K_];        // batch cluster size accumulator
__device__ float g_bes[K_ * D_];   // batch embedding sum accumulator
__device__ float g_cT[D_ * K_];    // codebook transposed [d][k]
__device__ float g_bsq[K_];        // ||c_k||^2

// ---------------- prep: zero accumulators, transpose codebook, b_sq ----------------
__global__ void vq_prep(const float* __restrict__ cb) {
    int i = blockIdx.x * blockDim.x + threadIdx.x;
    if (i < K_ * D_) {
        int k = i / D_, d = i % D_;
        g_cT[d * K_ + k] = cb[i];
        g_bes[i] = 0.0f;
    }
    if (i < K_) {
        g_bcs[i] = 0.0f;
        const float* row = cb + i * D_;
        // reference: jnp.sum(c*c, axis=1) -> mul then add, ascending, NO fma
        float s = 0.0f;
#pragma unroll
        for (int d = 0; d < D_; ++d) s = __fadd_rn(s, __fmul_rn(row[d], row[d]));
        g_bsq[i] = s;
    }
}

// ---------------- packed f32x2 helpers ----------------
__device__ __forceinline__ unsigned long long pack2(float lo, float hi) {
    unsigned long long r;
    asm("mov.b64 %0, {%1, %2};" : "=l"(r) : "f"(lo), "f"(hi));
    return r;
}
__device__ __forceinline__ void unpack2(unsigned long long v, float& lo, float& hi) {
    asm("mov.b64 {%0, %1}, %2;" : "=f"(lo), "=f"(hi) : "l"(v));
}
__device__ __forceinline__ void fma2(unsigned long long& acc, unsigned long long a,
                                     unsigned long long b) {
    asm("fma.rn.f32x2 %0, %1, %2, %0;" : "+l"(acc) : "l"(a), "l"(b));
}

// ---------------- main: distances + argmin + z_q_st + scatter stats ----------------
extern __shared__ float smem[];

__global__ void __launch_bounds__(THREADS) vq_main(
    const float* __restrict__ z, const float* __restrict__ cb,
    float* __restrict__ o_zq, float* __restrict__ o_idx, float* __restrict__ o_mind)
{
    float* sz  = smem;                 // [BM][ZS]  z tile, point-major
    float* sc  = sz + BM * ZS;         // [D_][CS]  codebook chunk, d-major
    float* sbs = sc + D_ * CS;         // [KC]      b_sq chunk
    int*   sidx = (int*)(sbs + KC);    // [BM]      winning index per point
    // reduction arrays alias sc (only used after all chunks are consumed)
    float* redv = sc;                  // [16][BM]
    int*   redi = (int*)(sc + 16 * BM);// [16][BM]

    const int tid = threadIdx.x;
    const int tx = tid & 15;           // code group
    const int ty = tid >> 4;           // point group
    const int p0 = blockIdx.x * BM;

    // load z tile (coalesced float4 reads, scalar smem writes)
    const float4* zg4 = (const float4*)(z + (size_t)p0 * D_);
    for (int i = tid; i < BM * D_ / 4; i += THREADS) {
        int p = i >> 4, q = i & 15;
        float4 v = zg4[p * 16 + q];
        float* dst = sz + p * ZS + q * 4;
        dst[0] = v.x; dst[1] = v.y; dst[2] = v.z; dst[3] = v.w;
    }
    __syncthreads();

    // a_sq for this thread's 8 points: sequential ascending, mul+add (NO fma),
    // replicating XLA's un-reassociated row reduction of z*z.
    float asq8[8];
#pragma unroll
    for (int p = 0; p < 8; ++p) {
        const float* zr = sz + (ty * 8 + p) * ZS;
        float a = 0.0f;
#pragma unroll
        for (int d = 0; d < D_; ++d) a = __fadd_rn(a, __fmul_rn(zr[d], zr[d]));
        asq8[p] = a;
    }

    float bestv[8];
    int   besti[8];
#pragma unroll
    for (int p = 0; p < 8; ++p) { bestv[p] = 3.4e38f; besti[p] = 0x7fffffff; }

    for (int ch = 0; ch < NCH; ++ch) {
        if (ch) __syncthreads();  // previous chunk fully consumed
        // load codebook chunk [64][128] from transposed global copy (coalesced)
        const float4* ct4 = (const float4*)g_cT;
        for (int i = tid; i < D_ * KC / 4; i += THREADS) {
            int d = i >> 5, j = i & 31;
            float4 v = ct4[(d * K_ + ch * KC) / 4 + j];
            *(float4*)(sc + d * CS + j * 4) = v;
        }
        if (tid < KC) sbs[tid] = g_bsq[ch * KC + tid];
        __syncthreads();

        // dot = sequential ascending-d single-accumulator fma chain
        // (f32x2 = two independent scalar fp32 fmas; same bit pattern as scalar chain)
        unsigned long long acc[8][4];
#pragma unroll
        for (int p = 0; p < 8; ++p)
#pragma unroll
            for (int c = 0; c < 4; ++c) acc[p][c] = 0ull;

#pragma unroll 8
        for (int d = 0; d < D_; ++d) {
            float4 ca = *(const float4*)(sc + d * CS + tx * 8);
            float4 cb4 = *(const float4*)(sc + d * CS + tx * 8 + 4);
            unsigned long long cc[4];
            cc[0] = pack2(ca.x, ca.y);  cc[1] = pack2(ca.z, ca.w);
            cc[2] = pack2(cb4.x, cb4.y); cc[3] = pack2(cb4.z, cb4.w);
#pragma unroll
            for (int p = 0; p < 8; ++p) {
                float zv = sz[(ty * 8 + p) * ZS + d];
                unsigned long long zz = pack2(zv, zv);
#pragma unroll
                for (int c = 0; c < 4; ++c) fma2(acc[p][c], zz, cc[c]);
            }
        }

        // epilogue: d = fl(fl(asq - fl(2*dot)) + bsq), exactly as the reference
        // expression (a_sq - 2.0*mm) + b_sq rounds. Lexicographic (val, idx) min.
#pragma unroll
        for (int p = 0; p < 8; ++p) {
#pragma unroll
            for (int c = 0; c < 4; ++c) {
                float lo, hi;
                unpack2(acc[p][c], lo, hi);
                int cidx = ch * KC + tx * 8 + c * 2;
                float bs0 = sbs[tx * 8 + c * 2];
                float bs1 = sbs[tx * 8 + c * 2 + 1];
                float t0 = __fsub_rn(asq8[p], __fmul_rn(2.0f, lo));  // 2*dot exact
                float t1 = __fsub_rn(asq8[p], __fmul_rn(2.0f, hi));
                float d0 = __fadd_rn(t0, bs0);
                float d1 = __fadd_rn(t1, bs1);
                if (d0 < bestv[p] || (d0 == bestv[p] && cidx < besti[p])) {
                    bestv[p] = d0; besti[p] = cidx;
                }
                if (d1 < bestv[p] || (d1 == bestv[p] && cidx + 1 < besti[p])) {
                    bestv[p] = d1; besti[p] = cidx + 1;
                }
            }
        }
    }

    __syncthreads();  // all compute reads of sc done -> safe to reuse as reduction space
#pragma unroll
    for (int p = 0; p < 8; ++p) {
        redv[tx * BM + ty * 8 + p] = bestv[p];
        redi[tx * BM + ty * 8 + p] = besti[p];
    }
    __syncthreads();

    if (tid < BM) {
        int p = tid;
        float bv = redv[p];
        int bi = redi[p];
#pragma unroll
        for (int t = 1; t < 16; ++t) {
            float v = redv[t * BM + p];
            int ii = redi[t * BM + p];
            if (v < bv || (v == bv && ii < bi)) { bv = v; bi = ii; }
        }
        o_idx[p0 + p]  = (float)bi;
        o_mind[p0 + p] = bv;               // already the full distance
        sidx[p] = bi;
        atomicAdd(&g_bcs[bi], 1.0f);
    }
    __syncthreads();

    // z_q_st (straight-through: z_e + (z_q - z_e), non-fused) + EMA scatter
    for (int i = tid; i < BM * D_; i += THREADS) {
        int p = i >> 6, d = i & 63;
        int bi = sidx[p];
        float ze = sz[p * ZS + d];
        float zq = cb[bi * D_ + d];
        o_zq[(size_t)(p0 + p) * D_ + d] = __fadd_rn(ze, __fsub_rn(zq, ze));
        atomicAdd(&g_bes[bi * D_ + d], ze);
    }
}

// ---------------- finalize: EMA update + new codebook ----------------
__global__ void vq_final(const float* __restrict__ ema_cs, const float* __restrict__ ema_es,
                         float* __restrict__ o_cb, float* __restrict__ o_cs,
                         float* __restrict__ o_es)
{
    int i = blockIdx.x * blockDim.x + threadIdx.x;
    if (i < K_) {
        o_cs[i] = __fadd_rn(__fmul_rn(0.99f, ema_cs[i]), __fmul_rn(0.01f, g_bcs[i]));
    }
    if (i < K_ * D_) {
        int k = i / D_;
        float ncs = __fadd_rn(__fmul_rn(0.99f, ema_cs[k]), __fmul_rn(0.01f, g_bcs[k]));
        float nes = __fadd_rn(__fmul_rn(0.99f, ema_es[i]), __fmul_rn(0.01f, g_bes[i]));
        o_es[i] = nes;
        o_cb[i] = __fdiv_rn(nes, __fadd_rn(ncs, 1e-5f));
    }
}

// ---------------- launcher ----------------
extern "C" void kernel_launch(void* const* d_in, const int* in_sizes, int n_in,
                              void* d_out, int out_size)
{
    const float* z      = (const float*)d_in[0];  // [512,512,64]
    const float* cb     = (const float*)d_in[1];  // [512,64]
    const float* ema_cs = (const float*)d_in[2];  // [512]
    const float* ema_es = (const float*)d_in[3];  // [512,64]

    float* out    = (float*)d_out;
    float* o_zq   = out;                              // N*D
    float* o_idx  = o_zq + (size_t)N_ * D_;           // N
    float* o_mind = o_idx + N_;                       // N
    float* o_cb   = o_mind + N_;                      // K*D
    float* o_cs   = o_cb + (size_t)K_ * D_;           // K
    float* o_es   = o_cs + K_;                        // K*D

    (void)in_sizes; (void)n_in; (void)out_size;

    vq_prep<<<(K_ * D_ + 255) / 256, 256>>>(cb);

    const size_t smem_bytes = (size_t)(BM * ZS + D_ * CS + KC + BM) * sizeof(float); // 68608
    cudaFuncSetAttribute(vq_main, cudaFuncAttributeMaxDynamicSharedMemorySize,
                         (int)smem_bytes);
    vq_main<<<N_ / BM, THREADS, smem_bytes>>>(z, cb, o_zq, o_idx, o_mind);

    vq_final<<<(K_ * D_ + 255) / 256, 256>>>(ema_cs, ema_es, o_cb, o_cs, o_es);
}